// round 17
// baseline (speedup 1.0000x reference)
#include <cuda_runtime.h>
#include <stdint.h>

// Pre-emphasis IIR y[i] = x[i] + 0.85*y[i-1]; out[o] = float(clip_int16(32768*y[o+91])),
// out[N-91..] = 0.
// R17: R12's winning geometry (4 samples/lane, 128-output windows, 4 windows/warp,
// exact 5-level weighted Kogge-Stone, in-register P31 chaining) made barrier-free:
// entering state from a per-warp 128-sample dot product (exactly 1 float4/lane:
// 3 FMA + scale + 5-shfl butterfly). No smem, no syncthreads, warps independent.
// 7 up-front LDG.128/lane (MLP 7); warmup re-reads are L2 hits.

namespace {
constexpr int   kThreads = 256;                 // 8 warps
constexpr int   kWin     = 128;                 // outputs per window (4/lane)
constexpr int   kWpw     = 4;                   // windows per warp
constexpr int   kSeg     = kWin * kWpw;         // 512 outputs per warp
constexpr int   kSkip    = 91;
constexpr float C1       = 0.85f;

constexpr float cp(int k) {
    float r = 1.0f;
    for (int i = 0; i < k; ++i) r *= 0.85f;
    return r;
}
// correction: true y_k = y_k + E * c^(k+1) within a 4-sample lane chunk
constexpr float A1 = cp(1), A2 = cp(2), A3 = cp(3), A4 = cp(4);
// Kogge-Stone merge weights (4 samples/lane) — 5 levels, exact
constexpr float K1 = cp(4), K2 = cp(8), K3 = cp(16), K4 = cp(32), K5 = cp(64);
constexpr float C2 = cp(2), C3 = cp(3);
}

// Saturating truncate-toward-zero to int16 range, back to float.
// Matches clip(-32768,32767) + astype(int16) exactly (f32->s16 cvt saturates).
__device__ __forceinline__ float q16(float v) {
    short q; asm("cvt.rzi.s16.f32 %0, %1;" : "=h"(q) : "f"(v));
    float r; asm("cvt.rn.f32.s16 %0, %1;" : "=f"(r) : "h"(q));
    return r;
}

template <bool EDGE>
__device__ __forceinline__ float4 ld4(const float* __restrict__ x, int e0, int n) {
    if (!EDGE) return *reinterpret_cast<const float4*>(x + e0);
    float4 v;
    v.x = (e0 + 0 >= 0 && e0 + 0 < n) ? x[e0 + 0] : 0.0f;
    v.y = (e0 + 1 >= 0 && e0 + 1 < n) ? x[e0 + 1] : 0.0f;
    v.z = (e0 + 2 >= 0 && e0 + 2 < n) ? x[e0 + 2] : 0.0f;
    v.w = (e0 + 3 >= 0 && e0 + 3 < n) ? x[e0 + 3] : 0.0f;
    return v;
}

// 5-level weighted Kogge-Stone over lane end-states (exact for 4 samples/lane)
__device__ __forceinline__ void ks5(float yEnd, int l, float& pex, float& P31) {
    const unsigned FULL = 0xffffffffu;
    float P = yEnd, u;
    u = __shfl_up_sync(FULL, P, 1);  P = (l >= 1)  ? fmaf(K1, u, P) : P;
    u = __shfl_up_sync(FULL, P, 2);  P = (l >= 2)  ? fmaf(K2, u, P) : P;
    u = __shfl_up_sync(FULL, P, 4);  P = (l >= 4)  ? fmaf(K3, u, P) : P;
    u = __shfl_up_sync(FULL, P, 8);  P = (l >= 8)  ? fmaf(K4, u, P) : P;
    u = __shfl_up_sync(FULL, P, 16); P = (l >= 16) ? fmaf(K5, u, P) : P;
    float pe = __shfl_up_sync(FULL, P, 1);
    pex = (l == 0) ? 0.0f : pe;
    P31 = __shfl_sync(FULL, P, 31);
}

template <bool EDGE>
__device__ __forceinline__ void warp_body(const float* __restrict__ x,
                                          float* __restrict__ out,
                                          int n, int nout, int O, int l)
{
    const unsigned FULL = 0xffffffffu;

    // ---- all loads up front (MLP ~7) ----
    // warmup: 128 samples x[O-40 .. O+88); head x[O+88..91) uniform broadcast.
    float4 wm = ld4<EDGE>(x, O - 40 + 4 * l, n);
    float4 hd = ld4<EDGE>(x, O + 88, n);               // uniform line
    float4 u[kWpw];
    #pragma unroll
    for (int j = 0; j < kWpw; ++j)
        u[j] = ld4<EDGE>(x, O + kWin * j + 88 + 4 * l, n);
    float4 ext = ld4<EDGE>(x, O + kWin * kWpw + 88, n);  // uniform line

    // ---- per-lane constants via bit decomposition ----
    float c4l = 1.0f;                    // c^(4l)
    if (l & 1)  c4l *= K1;
    if (l & 2)  c4l *= K2;
    if (l & 4)  c4l *= K3;
    if (l & 8)  c4l *= K4;
    if (l & 16) c4l *= K5;
    const int m = 31 - l;
    float c4m = C3;                      // c^(127-4l) = c^3 * c^(4(31-l))
    if (m & 1)  c4m *= K1;
    if (m & 2)  c4m *= K2;
    if (m & 4)  c4m *= K3;
    if (m & 8)  c4m *= K4;
    if (m & 16) c4m *= K5;

    // ---- warmup state: S = sum_{d>=0} c^d x[O+90-d] (128-sample truncation) ----
    float q = fmaf(C1, fmaf(C1, fmaf(C1, wm.x, wm.y), wm.z), wm.w);
    float p = q * c4m;
    p += __shfl_xor_sync(FULL, p, 16);
    p += __shfl_xor_sync(FULL, p, 8);
    p += __shfl_xor_sync(FULL, p, 4);
    p += __shfl_xor_sync(FULL, p, 2);
    p += __shfl_xor_sync(FULL, p, 1);
    float S = p + fmaf(C2, hd.x, fmaf(C1, hd.y, hd.z));

    // ---- 4 windows, carried in registers (S_next = P31; c^128 term ~ 2e-10) ----
    const int src = (l + 1) & 31;
    #pragma unroll
    for (int j = 0; j < kWpw; ++j) {
        // realign +3: next lane's u.{x,y,z}; lane 31 takes window j+1's lane-0 u
        // (or ext, uniform) via select-then-shfl.
        float tx = (l == 0) ? ((j < kWpw - 1) ? u[j + 1].x : ext.x) : u[j].x;
        float ty = (l == 0) ? ((j < kWpw - 1) ? u[j + 1].y : ext.y) : u[j].y;
        float tz = (l == 0) ? ((j < kWpw - 1) ? u[j + 1].z : ext.z) : u[j].z;
        float nx = __shfl_sync(FULL, tx, src);
        float ny = __shfl_sync(FULL, ty, src);
        float nz = __shfl_sync(FULL, tz, src);

        // lane-local 4-sample scan from zero state
        float y0 = u[j].w;
        float y1 = fmaf(C1, y0, nx);
        float y2 = fmaf(C1, y1, ny);
        float y3 = fmaf(C1, y2, nz);

        float pex, P31;
        ks5(y3, l, pex, P31);

        float E = fmaf(c4l, S, pex);
        S = P31;

        float4 o;
        o.x = q16(32768.0f * fmaf(A1, E, y0));
        o.y = q16(32768.0f * fmaf(A2, E, y1));
        o.z = q16(32768.0f * fmaf(A3, E, y2));
        o.w = q16(32768.0f * fmaf(A4, E, y3));

        const int ob = O + j * kWin;
        if (!EDGE) {
            reinterpret_cast<float4*>(out)[(ob >> 2) + l] = o;
        } else {
            const int oi = ob + 4 * l;
            const int zf = n - kSkip;            // outputs at/after this are 0
            float v[4] = {o.x, o.y, o.z, o.w};
            #pragma unroll
            for (int e = 0; e < 4; ++e)
                if (oi + e < nout)
                    out[oi + e] = (oi + e < zf) ? v[e] : 0.0f;
        }
    }
}

__global__ __launch_bounds__(kThreads, 6)
void preemph_f32_kernel(const float* __restrict__ x, float* __restrict__ out,
                        int n, int nout)
{
    const int wid = (blockIdx.x * kThreads + threadIdx.x) >> 5;
    const int l   = threadIdx.x & 31;
    const int O   = wid * kSeg;
    if (O >= nout) return;
    // interior: warmup load O-40 >= 0; max read O + kSeg + 91 < n;
    // outputs [O, O+kSeg) inside nout and before the zero tail (n-91).
    const bool edge = (O == 0) || (O + kSeg + 92 > n) || (O + kSeg > nout)
                   || (O + kSeg > n - kSkip);
    if (edge) warp_body<true >(x, out, n, nout, O, l);
    else      warp_body<false>(x, out, n, nout, O, l);
}

extern "C" void kernel_launch(void* const* d_in, const int* in_sizes, int n_in,
                              void* d_out, int out_size) {
    const float* x = (const float*)d_in[0];
    float* out = (float*)d_out;
    const int n = in_sizes[0];
    const int warps = (out_size + kSeg - 1) / kSeg;
    const int grid = (warps + (kThreads / 32) - 1) / (kThreads / 32);
    preemph_f32_kernel<<<grid, kThreads>>>(x, out, n, out_size);
}